// round 1
// baseline (speedup 1.0000x reference)
#include <cuda_runtime.h>
#include <math.h>

#define HID 51
#define GATES 204
#define GPAD 208      // padded gate rows (multiple of 8)
#define KPAD 52       // padded hidden dim (multiple of 4)
#define SEQL 999
#define BTILE 32
#define NWARP 8
#define NTHREADS 256
#define RPW 26        // rows per warp (GPAD / NWARP)
#define NBLOCKS 128   // BATCH / BTILE

struct Smem {
    float W[GPAD * KPAD];     // W_hh padded: [row][k]
    float gates[GPAD * 32];   // [row][lane]
    float h[KPAD * 32];       // [k][lane]
    float wih[GPAD];
    float bsum[GPAD];         // b_ih + b_hh
    float wfc[64];
    float ypart[NWARP * 32];
};

__device__ __forceinline__ float sigmoid_f(float x) {
    // 1/(1+e^-x) via fast exp; accurate to ~2ulp over relevant range
    return 1.0f / (1.0f + __expf(-x));
}
__device__ __forceinline__ float tanh_f(float x) {
    float ax = fabsf(x);
    float e = __expf(-2.0f * ax);            // in (0,1]
    float t = (1.0f - e) / (1.0f + e);
    return copysignf(t, x);
}

extern __shared__ float smem_raw[];

__global__ __launch_bounds__(NTHREADS, 1)
void lstm_kernel(const float* __restrict__ input,
                 const float* __restrict__ W_ih,
                 const float* __restrict__ W_hh,
                 const float* __restrict__ b_ih,
                 const float* __restrict__ b_hh,
                 const float* __restrict__ W_fc,
                 const float* __restrict__ b_fc,
                 float* __restrict__ out)
{
    Smem* s = (Smem*)smem_raw;
    const int tid = threadIdx.x;
    const int w   = tid >> 5;
    const int l   = tid & 31;
    const int b   = blockIdx.x * BTILE + l;

    // ---- cooperative weight load into shared (once) ----
    for (int idx = tid; idx < GPAD * KPAD; idx += NTHREADS) {
        int r = idx / KPAD, k = idx - r * KPAD;
        s->W[idx] = (r < GATES && k < HID) ? W_hh[r * HID + k] : 0.0f;
    }
    for (int r = tid; r < GPAD; r += NTHREADS) {
        bool v = (r < GATES);
        s->wih[r]  = v ? W_ih[r] : 0.0f;
        s->bsum[r] = v ? (b_ih[r] + b_hh[r]) : 0.0f;
    }
    if (tid < 64) s->wfc[tid] = (tid < HID) ? W_fc[tid] : 0.0f;
    for (int idx = tid; idx < KPAD * 32; idx += NTHREADS) s->h[idx] = 0.0f;
    const float bfc = b_fc[0];
    __syncthreads();

    // c-state lives in registers: thread (w,l) owns hidden j = w + 8*i of batch b
    float c[7];
    #pragma unroll
    for (int i = 0; i < 7; i++) c[i] = 0.0f;
    const int nj = (w < 3) ? 7 : 6;   // j = w + 8*i < 51

    const float* __restrict__ xin = input + (size_t)b * SEQL;

    for (int t = 0; t < SEQL; t++) {
        // ---------------- phase 1: gate matvec ----------------
        const float x = xin[t];
        float acc[RPW];
        #pragma unroll
        for (int i = 0; i < RPW; i++) {
            int r = w + 8 * i;
            acc[i] = fmaf(s->wih[r], x, s->bsum[r]);
        }
        const float* Wbase = &s->W[w * KPAD];
        for (int k = 0; k < KPAD; k += 4) {
            float h0 = s->h[(k + 0) * 32 + l];
            float h1 = s->h[(k + 1) * 32 + l];
            float h2 = s->h[(k + 2) * 32 + l];
            float h3 = s->h[(k + 3) * 32 + l];
            #pragma unroll
            for (int i = 0; i < RPW; i++) {
                const float4 wv = *(const float4*)(Wbase + i * (8 * KPAD) + k);
                acc[i] = fmaf(wv.x, h0, acc[i]);
                acc[i] = fmaf(wv.y, h1, acc[i]);
                acc[i] = fmaf(wv.z, h2, acc[i]);
                acc[i] = fmaf(wv.w, h3, acc[i]);
            }
        }
        #pragma unroll
        for (int i = 0; i < RPW; i++)
            s->gates[(w + 8 * i) * 32 + l] = acc[i];
        __syncthreads();

        // ---------------- phase 2: state update ----------------
        float yp = 0.0f;
        #pragma unroll
        for (int i = 0; i < 7; i++) {
            if (i < nj) {
                int j = w + 8 * i;
                float ig = s->gates[j * 32 + l];
                float fg = s->gates[(HID + j) * 32 + l];
                float gg = s->gates[(2 * HID + j) * 32 + l];
                float og = s->gates[(3 * HID + j) * 32 + l];
                float ci = sigmoid_f(fg) * c[i] + sigmoid_f(ig) * tanh_f(gg);
                c[i] = ci;
                float hn = sigmoid_f(og) * tanh_f(ci);
                s->h[j * 32 + l] = hn;
                yp = fmaf(s->wfc[j], hn, yp);
            }
        }
        s->ypart[w * 32 + l] = yp;
        __syncthreads();

        // ---------------- phase 3: output (warp 0) ----------------
        if (w == 0) {
            float y = bfc;
            #pragma unroll
            for (int ww = 0; ww < NWARP; ww++) y += s->ypart[ww * 32 + l];
            out[(size_t)b * SEQL + t] = y;
        }
    }
}

extern "C" void kernel_launch(void* const* d_in, const int* in_sizes, int n_in,
                              void* d_out, int out_size) {
    const float* input = (const float*)d_in[0];
    const float* W_ih  = (const float*)d_in[1];
    const float* W_hh  = (const float*)d_in[2];
    const float* b_ih  = (const float*)d_in[3];
    const float* b_hh  = (const float*)d_in[4];
    const float* W_fc  = (const float*)d_in[5];
    const float* b_fc  = (const float*)d_in[6];
    // d_in[7] = future (static 0 in this problem) — ignored.

    cudaFuncSetAttribute(lstm_kernel,
                         cudaFuncAttributeMaxDynamicSharedMemorySize,
                         (int)sizeof(Smem));
    lstm_kernel<<<NBLOCKS, NTHREADS, sizeof(Smem)>>>(
        input, W_ih, W_hh, b_ih, b_hh, W_fc, b_fc, (float*)d_out);
}

// round 2
// speedup vs baseline: 1.4754x; 1.4754x over previous
#include <cuda_runtime.h>
#include <math.h>

#define HID 51
#define GATES 204
#define GPAD 208      // padded gate rows (multiple of 16)
#define KPAD 52       // padded hidden dim (multiple of 4)
#define NKP 26        // k-pairs (KPAD/2)
#define SEQL 999
#define BTILE 32
#define NWARP 16
#define NTHREADS 512
#define RPW 13        // rows per warp (GPAD / NWARP)
#define NBLOCKS 128   // BATCH / BTILE

typedef unsigned long long u64;

struct Smem {
    float  W[GPAD * KPAD];     // W_hh padded: [row][k], 16B-aligned rows
    float  gates[GPAD * 32];   // [row][lane]
    float2 h2[NKP * 32];       // [kpair][lane] = (h_{2p}, h_{2p+1})
    float  wih[GPAD];
    float  bsum[GPAD];         // b_ih + b_hh
    float  wfc[64];
    float  ypart[NWARP * 32];
};

__device__ __forceinline__ void fma2(u64& acc, u64 a, u64 b) {
    asm("fma.rn.f32x2 %0, %1, %2, %0;" : "+l"(acc) : "l"(a), "l"(b));
}
__device__ __forceinline__ u64 pack2(float lo, float hi) {
    u64 r; asm("mov.b64 %0, {%1, %2};" : "=l"(r) : "f"(lo), "f"(hi)); return r;
}
__device__ __forceinline__ void unpack2(u64 v, float& lo, float& hi) {
    asm("mov.b64 {%0, %1}, %2;" : "=f"(lo), "=f"(hi) : "l"(v));
}
__device__ __forceinline__ float tanh_a(float x) {
    float y; asm("tanh.approx.f32 %0, %1;" : "=f"(y) : "f"(x)); return y;
}
__device__ __forceinline__ float sigm(float x) {
    return fmaf(tanh_a(0.5f * x), 0.5f, 0.5f);
}

extern __shared__ float smem_raw[];

__global__ __launch_bounds__(NTHREADS, 1)
void lstm_kernel(const float* __restrict__ input,
                 const float* __restrict__ W_ih,
                 const float* __restrict__ W_hh,
                 const float* __restrict__ b_ih,
                 const float* __restrict__ b_hh,
                 const float* __restrict__ W_fc,
                 const float* __restrict__ b_fc,
                 float* __restrict__ out)
{
    Smem* s = (Smem*)smem_raw;
    const int tid = threadIdx.x;
    const int w   = tid >> 5;
    const int l   = tid & 31;
    const int b   = blockIdx.x * BTILE + l;

    // ---- cooperative init (once) ----
    for (int idx = tid; idx < GPAD * KPAD; idx += NTHREADS) {
        int r = idx / KPAD, k = idx - r * KPAD;
        s->W[idx] = (r < GATES && k < HID) ? W_hh[r * HID + k] : 0.0f;
    }
    for (int r = tid; r < GPAD; r += NTHREADS) {
        bool v = (r < GATES);
        s->wih[r]  = v ? W_ih[r] : 0.0f;
        s->bsum[r] = v ? (b_ih[r] + b_hh[r]) : 0.0f;
    }
    if (tid < 64) s->wfc[tid] = (tid < HID) ? W_fc[tid] : 0.0f;
    {
        float* h2f = (float*)s->h2;
        for (int idx = tid; idx < NKP * 32 * 2; idx += NTHREADS) h2f[idx] = 0.0f;
    }
    const float bfc = b_fc[0];
    __syncthreads();

    // c-state in registers: thread (w,l) owns hidden j = w + 16*i of batch b
    float c[4];
    #pragma unroll
    for (int i = 0; i < 4; i++) c[i] = 0.0f;

    const float* __restrict__ xin = input + (size_t)b * SEQL;
    const float* Wbase = s->W + w * KPAD;   // row stride between i's = 16*KPAD floats

    for (int t = 0; t < SEQL; t++) {
        // ---------------- phase 1: gate matvec (packed f32x2 along k) ----------------
        const float x = xin[t];
        u64 acc[RPW];
        #pragma unroll
        for (int i = 0; i < RPW; i++) {
            int r = w + 16 * i;
            acc[i] = pack2(fmaf(s->wih[r], x, s->bsum[r]), 0.0f);
        }
        for (int q = 0; q < KPAD / 4; q++) {       // 13 k-quads
            u64 h0 = *(const u64*)&s->h2[(2 * q + 0) * 32 + l];
            u64 h1 = *(const u64*)&s->h2[(2 * q + 1) * 32 + l];
            #pragma unroll
            for (int i = 0; i < RPW; i++) {
                const ulonglong2 wv =
                    *(const ulonglong2*)(Wbase + i * (16 * KPAD) + 4 * q);
                fma2(acc[i], wv.x, h0);
                fma2(acc[i], wv.y, h1);
            }
        }
        #pragma unroll
        for (int i = 0; i < RPW; i++) {
            float lo, hi; unpack2(acc[i], lo, hi);
            s->gates[(w + 16 * i) * 32 + l] = lo + hi;
        }
        __syncthreads();

        // ---------------- phase 2: state update ----------------
        float yp = 0.0f;
        float* h2f = (float*)s->h2;
        #pragma unroll
        for (int i = 0; i < 4; i++) {
            int j = w + 16 * i;
            if (j < HID) {
                float ig = s->gates[j * 32 + l];
                float fg = s->gates[(HID + j) * 32 + l];
                float gg = s->gates[(2 * HID + j) * 32 + l];
                float og = s->gates[(3 * HID + j) * 32 + l];
                float ci = sigm(fg) * c[i] + sigm(ig) * tanh_a(gg);
                c[i] = ci;
                float hn = sigm(og) * tanh_a(ci);
                h2f[(j >> 1) * 64 + 2 * l + (j & 1)] = hn;
                yp = fmaf(s->wfc[j], hn, yp);
            }
        }
        s->ypart[w * 32 + l] = yp;
        __syncthreads();

        // ---------------- phase 3: output (warp 0) ----------------
        if (w == 0) {
            float y = bfc;
            #pragma unroll
            for (int ww = 0; ww < NWARP; ww++) y += s->ypart[ww * 32 + l];
            out[(size_t)b * SEQL + t] = y;
        }
    }
}

extern "C" void kernel_launch(void* const* d_in, const int* in_sizes, int n_in,
                              void* d_out, int out_size) {
    const float* input = (const float*)d_in[0];
    const float* W_ih  = (const float*)d_in[1];
    const float* W_hh  = (const float*)d_in[2];
    const float* b_ih  = (const float*)d_in[3];
    const float* b_hh  = (const float*)d_in[4];
    const float* W_fc  = (const float*)d_in[5];
    const float* b_fc  = (const float*)d_in[6];
    // d_in[7] = future (static 0) — ignored.

    cudaFuncSetAttribute(lstm_kernel,
                         cudaFuncAttributeMaxDynamicSharedMemorySize,
                         (int)sizeof(Smem));
    lstm_kernel<<<NBLOCKS, NTHREADS, sizeof(Smem)>>>(
        input, W_ih, W_hh, b_ih, b_hh, W_fc, b_fc, (float*)d_out);
}

// round 4
// speedup vs baseline: 2.6051x; 1.7657x over previous
#include <cuda_runtime.h>
#include <cstdint>

#define HID 51
#define SEQL 999
#define NTHREADS 512
#define NBLOCKS 128
#define NMMA 13          // warps doing MMA (13*16 = 208 gate rows)
#define GSTRIDE 36       // gates smem row stride (conflict-free for frag stores)

// smem float offsets
#define AHI_OFF 0                      // A-hi fragments: 14 frags x 128 floats
#define ALO_OFF (14*128)               // A-lo fragments
#define G_OFF   (ALO_OFF + 14*128)     // gates[g][b], stride GSTRIDE
#define WFC_OFF (G_OFF + 208*GSTRIDE)
#define SMEM_FLOATS (WFC_OFF + 64)

__device__ __forceinline__ float tf32r(float x) {
    float y; asm("cvt.rna.tf32.f32 %0, %1;" : "=f"(y) : "f"(x)); return y;
}
__device__ __forceinline__ float tanh_a(float x) {
    float y; asm("tanh.approx.f32 %0, %1;" : "=f"(y) : "f"(x)); return y;
}
__device__ __forceinline__ float sigm(float x) {
    return fmaf(tanh_a(0.5f * x), 0.5f, 0.5f);
}
__device__ __forceinline__ void mma_t(float& d0, float& d1, float& d2, float& d3,
                                      uint32_t a0, uint32_t a1, uint32_t a2, uint32_t a3,
                                      uint32_t b0, uint32_t b1) {
    asm volatile("mma.sync.aligned.m16n8k8.row.col.f32.tf32.tf32.f32 "
                 "{%0,%1,%2,%3}, {%4,%5,%6,%7}, {%8,%9}, {%0,%1,%2,%3};"
                 : "+f"(d0), "+f"(d1), "+f"(d2), "+f"(d3)
                 : "r"(a0), "r"(a1), "r"(a2), "r"(a3), "r"(b0), "r"(b1));
}

// position of element A[b][k] inside fragment-major A storage (floats)
__device__ __forceinline__ int afrag_addr(int b, int k) {
    int mt = b >> 4, rp = b & 15;
    int kc = k >> 3, kk = k & 7;
    int slot = ((rp >> 3) & 1) + ((kk >> 2) << 1);
    int tp = (rp & 7) * 4 + (kk & 3);
    return (mt * 7 + kc) * 128 + tp * 4 + slot;
}

__shared__ __align__(16) float sm[SMEM_FLOATS];

__global__ __launch_bounds__(NTHREADS, 1)
void lstm_mma_kernel(const float* __restrict__ input,
                     const float* __restrict__ W_ih,
                     const float* __restrict__ W_hh,
                     const float* __restrict__ b_ih,
                     const float* __restrict__ b_hh,
                     const float* __restrict__ W_fc,
                     const float* __restrict__ b_fc,
                     float* __restrict__ out)
{
    const int tid = threadIdx.x;
    const int w   = tid >> 5;
    const int l   = tid & 31;

    // ---- weight B-fragments into registers (MMA warps own 16 gate rows each) ----
    uint32_t whi[7][2][2], wlo[7][2][2];
    if (w < NMMA) {
        #pragma unroll
        for (int kc = 0; kc < 7; kc++)
        #pragma unroll
        for (int nt = 0; nt < 2; nt++)
        #pragma unroll
        for (int hf = 0; hf < 2; hf++) {
            int g  = w * 16 + nt * 8 + (l >> 2);
            int kk = kc * 8 + (l & 3) + hf * 4;
            float v = 0.0f;
            if (g < 204) {
                if (kk < HID)      v = W_hh[g * HID + kk];
                else if (kk == 51) v = W_ih[g];
                else if (kk == 52) v = b_ih[g] + b_hh[g];
            }
            float vh = tf32r(v);
            whi[kc][nt][hf] = __float_as_uint(vh);
            wlo[kc][nt][hf] = __float_as_uint(tf32r(v - vh));
        }
    }

    // ---- smem init ----
    for (int i = tid; i < 2 * 14 * 128; i += NTHREADS) sm[AHI_OFF + i] = 0.0f;
    if (tid < 64) sm[WFC_OFF + tid] = (tid < HID) ? W_fc[tid] : 0.0f;
    __syncthreads();
    if (tid < 32) {
        int b = tid;
        sm[AHI_OFF + afrag_addr(b, 52)] = 1.0f;   // bias column
        float x  = input[(size_t)(blockIdx.x * 32 + b) * SEQL];
        float xh = tf32r(x);
        sm[AHI_OFF + afrag_addr(b, 51)] = xh;
        sm[ALO_OFF + afrag_addr(b, 51)] = tf32r(x - xh);
    }
    const float bfc = b_fc[0];
    __syncthreads();

    // phase-2 mapping: thread (bl, l4) owns batch bl, hidden j = l4 + 16*i
    const int bl = tid >> 4;
    const int l4 = tid & 15;
    float cst[4] = {0.0f, 0.0f, 0.0f, 0.0f};
    const float* __restrict__ xin = input + (size_t)(blockIdx.x * 32 + bl) * SEQL;
    float* __restrict__ yout = out + (size_t)(blockIdx.x * 32 + bl) * SEQL;

    for (int t = 0; t < SEQL; t++) {
        // ---------------- phase 1: gates = h · Wᵀ (tf32 mma, 3-term) ----------------
        if (w < NMMA) {
            float acc[2][2][4];
            #pragma unroll
            for (int mt = 0; mt < 2; mt++)
            #pragma unroll
            for (int nt = 0; nt < 2; nt++)
            #pragma unroll
            for (int r = 0; r < 4; r++) acc[mt][nt][r] = 0.0f;

            #pragma unroll
            for (int kc = 0; kc < 7; kc++) {
                const float4 h0 = *(const float4*)&sm[AHI_OFF + kc * 128 + l * 4];
                const float4 h1 = *(const float4*)&sm[AHI_OFF + (7 + kc) * 128 + l * 4];
                const float4 e0 = *(const float4*)&sm[ALO_OFF + kc * 128 + l * 4];
                const float4 e1 = *(const float4*)&sm[ALO_OFF + (7 + kc) * 128 + l * 4];
                uint32_t h0a = __float_as_uint(h0.x), h0b = __float_as_uint(h0.y),
                         h0c = __float_as_uint(h0.z), h0d = __float_as_uint(h0.w);
                uint32_t h1a = __float_as_uint(h1.x), h1b = __float_as_uint(h1.y),
                         h1c = __float_as_uint(h1.z), h1d = __float_as_uint(h1.w);
                uint32_t e0a = __float_as_uint(e0.x), e0b = __float_as_uint(e0.y),
                         e0c = __float_as_uint(e0.z), e0d = __float_as_uint(e0.w);
                uint32_t e1a = __float_as_uint(e1.x), e1b = __float_as_uint(e1.y),
                         e1c = __float_as_uint(e1.z), e1d = __float_as_uint(e1.w);
                #pragma unroll
                for (int nt = 0; nt < 2; nt++) {
                    uint32_t bh0 = whi[kc][nt][0], bh1 = whi[kc][nt][1];
                    uint32_t bl0 = wlo[kc][nt][0], bl1 = wlo[kc][nt][1];
                    mma_t(acc[0][nt][0], acc[0][nt][1], acc[0][nt][2], acc[0][nt][3],
                          h0a, h0b, h0c, h0d, bh0, bh1);
                    mma_t(acc[1][nt][0], acc[1][nt][1], acc[1][nt][2], acc[1][nt][3],
                          h1a, h1b, h1c, h1d, bh0, bh1);
                    mma_t(acc[0][nt][0], acc[0][nt][1], acc[0][nt][2], acc[0][nt][3],
                          h0a, h0b, h0c, h0d, bl0, bl1);
                    mma_t(acc[1][nt][0], acc[1][nt][1], acc[1][nt][2], acc[1][nt][3],
                          h1a, h1b, h1c, h1d, bl0, bl1);
                    mma_t(acc[0][nt][0], acc[0][nt][1], acc[0][nt][2], acc[0][nt][3],
                          e0a, e0b, e0c, e0d, bh0, bh1);
                    mma_t(acc[1][nt][0], acc[1][nt][1], acc[1][nt][2], acc[1][nt][3],
                          e1a, e1b, e1c, e1d, bh0, bh1);
                }
            }
            // store gates[g][b]
            #pragma unroll
            for (int mt = 0; mt < 2; mt++)
            #pragma unroll
            for (int nt = 0; nt < 2; nt++) {
                int g0 = w * 16 + nt * 8 + (l & 3) * 2;
                int b0 = mt * 16 + (l >> 2);
                sm[G_OFF + g0 * GSTRIDE + b0]           = acc[mt][nt][0];
                sm[G_OFF + (g0 + 1) * GSTRIDE + b0]     = acc[mt][nt][1];
                sm[G_OFF + g0 * GSTRIDE + b0 + 8]       = acc[mt][nt][2];
                sm[G_OFF + (g0 + 1) * GSTRIDE + b0 + 8] = acc[mt][nt][3];
            }
        }
        __syncthreads();

        // ---------------- phase 2: activations + state + y ----------------
        {
            float yp = 0.0f;
            #pragma unroll
            for (int i = 0; i < 4; i++) {
                int j = l4 + 16 * i;
                if (j < HID) {
                    float ig = sm[G_OFF + j * GSTRIDE + bl];
                    float fg = sm[G_OFF + (HID + j) * GSTRIDE + bl];
                    float gg = sm[G_OFF + (2 * HID + j) * GSTRIDE + bl];
                    float og = sm[G_OFF + (3 * HID + j) * GSTRIDE + bl];
                    float cn = fmaf(sigm(fg), cst[i], sigm(ig) * tanh_a(gg));
                    cst[i] = cn;
                    float h  = sigm(og) * tanh_a(cn);
                    float hh = tf32r(h);
                    int ad = afrag_addr(bl, j);
                    sm[AHI_OFF + ad] = hh;
                    sm[ALO_OFF + ad] = tf32r(h - hh);
                    yp = fmaf(sm[WFC_OFF + j], h, yp);
                }
            }
            yp += __shfl_xor_sync(0xFFFFFFFFu, yp, 8);
            yp += __shfl_xor_sync(0xFFFFFFFFu, yp, 4);
            yp += __shfl_xor_sync(0xFFFFFFFFu, yp, 2);
            yp += __shfl_xor_sync(0xFFFFFFFFu, yp, 1);
            if (l4 == 0) {
                yout[t] = yp + bfc;
                float xn = (t + 1 < SEQL) ? xin[t + 1] : 0.0f;
                float xh = tf32r(xn);
                int ax = afrag_addr(bl, 51);
                sm[AHI_OFF + ax] = xh;
                sm[ALO_OFF + ax] = tf32r(xn - xh);
            }
        }
        __syncthreads();
    }
}

extern "C" void kernel_launch(void* const* d_in, const int* in_sizes, int n_in,
                              void* d_out, int out_size) {
    const float* input = (const float*)d_in[0];
    const float* W_ih  = (const float*)d_in[1];
    const float* W_hh  = (const float*)d_in[2];
    const float* b_ih  = (const float*)d_in[3];
    const float* b_hh  = (const float*)d_in[4];
    const float* W_fc  = (const float*)d_in[5];
    const float* b_fc  = (const float*)d_in[6];
    // d_in[7] = future (static 0) — ignored.

    lstm_mma_kernel<<<NBLOCKS, NTHREADS>>>(
        input, W_ih, W_hh, b_ih, b_hh, W_fc, b_fc, (float*)d_out);
}

// round 5
// speedup vs baseline: 4.3153x; 1.6565x over previous
#include <cuda_runtime.h>
#include <cuda_bf16.h>
#include <cstdint>

#define HID 51
#define SEQL 999
#define NTHREADS 512
#define NBLOCKS 128

// A fragments: [parity][mt][kc][s(hi/lo)], each 512B (lane*16 holds a0..a3)
struct SM {
    uint8_t abuf[2][2][4][2][512];
    float   ypart[2][7][32];
};
__shared__ SM sm;

__device__ __forceinline__ float tanh_a(float x) {
    float y; asm("tanh.approx.f32 %0, %1;" : "=f"(y) : "f"(x)); return y;
}
__device__ __forceinline__ float sigm(float x) {
    return fmaf(tanh_a(0.5f * x), 0.5f, 0.5f);
}
__device__ __forceinline__ void mma_bf16(float* d, const uint32_t* a, const uint32_t* b) {
    asm volatile("mma.sync.aligned.m16n8k16.row.col.f32.bf16.bf16.f32 "
                 "{%0,%1,%2,%3}, {%4,%5,%6,%7}, {%8,%9}, {%0,%1,%2,%3};"
                 : "+f"(d[0]), "+f"(d[1]), "+f"(d[2]), "+f"(d[3])
                 : "r"(a[0]), "r"(a[1]), "r"(a[2]), "r"(a[3]), "r"(b[0]), "r"(b[1]));
}
// byte offset of A element (row rp 0..15, col kk 0..15) inside a 512B frag
__device__ __forceinline__ int frag_off(int rp, int kk) {
    int lane = (rp & 7) * 4 + ((kk & 7) >> 1);
    int reg  = ((rp >> 3) & 1) + 2 * ((kk >> 3) & 1);
    return lane * 16 + reg * 4 + (kk & 1) * 2;
}
__device__ __forceinline__ uint32_t pkbf2(float v0, float v1) {
    uint32_t a = __bfloat16_as_ushort(__float2bfloat16(v0));
    uint32_t b = __bfloat16_as_ushort(__float2bfloat16(v1));
    return a | (b << 16);
}

__global__ __launch_bounds__(NTHREADS, 1)
void lstm_bf16_kernel(const float* __restrict__ input,
                      const float* __restrict__ W_ih,
                      const float* __restrict__ W_hh,
                      const float* __restrict__ b_ih,
                      const float* __restrict__ b_hh,
                      const float* __restrict__ W_fc,
                      const float* __restrict__ b_fc,
                      float* __restrict__ out)
{
    const int tid = threadIdx.x;
    const int w   = tid >> 5;
    const int l   = tid & 31;
    const int gg  = w >> 1;        // gate group 0..6 (32 interleaved gate cols)
    const int mt  = w & 1;         // batch half (16 rows)
    const int r4  = l & 3;
    const int q   = l >> 2;

    // ---- zero A buffers (both parities) ----
    {
        uint32_t* p = (uint32_t*)sm.abuf;
        for (int i = tid; i < (int)(sizeof(sm.abuf) / 4); i += NTHREADS) p[i] = 0;
    }
    __syncthreads();
    // bias col (k=52) = 1.0 in both parities; x(0) into parity 0 (k=51)
    if (tid < 32) {
        int bmt = tid >> 4, rp = tid & 15;
        for (int par = 0; par < 2; par++)
            *(uint16_t*)&sm.abuf[par][bmt][3][0][frag_off(rp, 4)] = 0x3F80; // bf16 1.0
        float x = input[(size_t)(blockIdx.x * 32 + tid) * SEQL];
        __nv_bfloat16 xh = __float2bfloat16(x);
        __nv_bfloat16 xl = __float2bfloat16(x - __bfloat162float(xh));
        *(__nv_bfloat16*)&sm.abuf[0][bmt][3][0][frag_off(rp, 3)] = xh;
        *(__nv_bfloat16*)&sm.abuf[0][bmt][3][1][frag_off(rp, 3)] = xl;
    }

    // ---- weight fragments into registers (interleaved gate columns) ----
    // col = gg*32 + nt*8 + n maps to hidden j = col>>2, gate qg = col&3,
    // original row = qg*51 + j.
    uint32_t wh[4][4][2], wl[4][4][2];
    float wfcj[4];
    if (w < 14) {
        #pragma unroll
        for (int kc = 0; kc < 4; kc++)
        #pragma unroll
        for (int nt = 0; nt < 4; nt++)
        #pragma unroll
        for (int e = 0; e < 2; e++) {
            int col = gg * 32 + nt * 8 + q;
            int j = col >> 2, qg = col & 3;
            int k0 = kc * 16 + r4 * 2 + e * 8;
            float v0 = 0.0f, v1 = 0.0f;
            if (j < HID) {
                int row = qg * HID + j;
                #pragma unroll
                for (int hlf = 0; hlf < 2; hlf++) {
                    int k = k0 + hlf;
                    float v = 0.0f;
                    if (k < HID)       v = W_hh[row * HID + k];
                    else if (k == 51)  v = W_ih[row];
                    else if (k == 52)  v = b_ih[row] + b_hh[row];
                    if (hlf) v1 = v; else v0 = v;
                }
            }
            float h0 = __bfloat162float(__float2bfloat16(v0));
            float h1 = __bfloat162float(__float2bfloat16(v1));
            wh[kc][nt][e] = pkbf2(v0, v1);           // rounds inside
            wl[kc][nt][e] = pkbf2(v0 - h0, v1 - h1);
        }
        #pragma unroll
        for (int nt = 0; nt < 4; nt++) {
            int j = gg * 8 + nt * 2 + (r4 >> 1);
            wfcj[nt] = (j < HID) ? W_fc[j] : 0.0f;
        }
    }
    const float bfc = b_fc[0];
    __syncthreads();

    float cst[4] = {0.0f, 0.0f, 0.0f, 0.0f};
    const bool even = !(r4 & 1);
    const int rp_mine = q + (even ? 0 : 8);          // my batch row within mt tile

    for (int t = 0; t < SEQL; t++) {
        const int par = t & 1;
        if (w < 14) {
            // ---- phase 1: 48 HMMA (bf16 3-term) ----
            float acc[4][4];
            #pragma unroll
            for (int nt = 0; nt < 4; nt++)
            #pragma unroll
            for (int i = 0; i < 4; i++) acc[nt][i] = 0.0f;

            #pragma unroll
            for (int kc = 0; kc < 4; kc++) {
                uint32_t Ah[4], Al[4];
                *(uint4*)Ah = *(const uint4*)&sm.abuf[par][mt][kc][0][l * 16];
                *(uint4*)Al = *(const uint4*)&sm.abuf[par][mt][kc][1][l * 16];
                #pragma unroll
                for (int nt = 0; nt < 4; nt++) {
                    mma_bf16(acc[nt], Ah, wh[kc][nt]);
                    mma_bf16(acc[nt], Al, wh[kc][nt]);
                    mma_bf16(acc[nt], Ah, wl[kc][nt]);
                }
            }

            // ---- phase 2: in-warp gate exchange + LSTM update ----
            float yp = 0.0f;
            #pragma unroll
            for (int nt = 0; nt < 4; nt++) {
                float v0 = even ? acc[nt][2] : acc[nt][0];
                float v1 = even ? acc[nt][3] : acc[nt][1];
                float e0 = __shfl_xor_sync(0xFFFFFFFFu, v0, 1);
                float e1 = __shfl_xor_sync(0xFFFFFFFFu, v1, 1);
                float gi = even ? acc[nt][0] : e0;
                float gf = even ? acc[nt][1] : e1;
                float gG = even ? e0 : acc[nt][2];
                float gO = even ? e1 : acc[nt][3];
                float cn = fmaf(sigm(gf), cst[nt], sigm(gi) * tanh_a(gG));
                cst[nt] = cn;
                float h = sigm(gO) * tanh_a(cn);
                int j = gg * 8 + nt * 2 + (r4 >> 1);
                if (j < HID) {
                    __nv_bfloat16 hh = __float2bfloat16(h);
                    __nv_bfloat16 hl = __float2bfloat16(h - __bfloat162float(hh));
                    int fo = frag_off(rp_mine, j & 15);
                    *(__nv_bfloat16*)&sm.abuf[par ^ 1][mt][j >> 4][0][fo] = hh;
                    *(__nv_bfloat16*)&sm.abuf[par ^ 1][mt][j >> 4][1][fo] = hl;
                    yp = fmaf(wfcj[nt], h, yp);
                }
            }
            yp += __shfl_xor_sync(0xFFFFFFFFu, yp, 2);
            if (r4 < 2)
                sm.ypart[par][gg][mt * 16 + q + r4 * 8] = yp;
        } else if (w == 14) {
            // stage x(t+1) into next-parity A; emit y(t-1)
            if (t + 1 < SEQL) {
                float x = input[(size_t)(blockIdx.x * 32 + l) * SEQL + t + 1];
                __nv_bfloat16 xh = __float2bfloat16(x);
                __nv_bfloat16 xl = __float2bfloat16(x - __bfloat162float(xh));
                int fo = frag_off(l & 15, 3);
                *(__nv_bfloat16*)&sm.abuf[par ^ 1][l >> 4][3][0][fo] = xh;
                *(__nv_bfloat16*)&sm.abuf[par ^ 1][l >> 4][3][1][fo] = xl;
            }
            if (t > 0) {
                float y = bfc;
                #pragma unroll
                for (int g2 = 0; g2 < 7; g2++) y += sm.ypart[par ^ 1][g2][l];
                out[(size_t)(blockIdx.x * 32 + l) * SEQL + (t - 1)] = y;
            }
        }
        __syncthreads();
    }

    // final y(SEQL-1)
    if (w == 14) {
        float y = bfc;
        #pragma unroll
        for (int g2 = 0; g2 < 7; g2++) y += sm.ypart[(SEQL - 1) & 1][g2][l];
        out[(size_t)(blockIdx.x * 32 + l) * SEQL + (SEQL - 1)] = y;
    }
}

extern "C" void kernel_launch(void* const* d_in, const int* in_sizes, int n_in,
                              void* d_out, int out_size) {
    const float* input = (const float*)d_in[0];
    const float* W_ih  = (const float*)d_in[1];
    const float* W_hh  = (const float*)d_in[2];
    const float* b_ih  = (const float*)d_in[3];
    const float* b_hh  = (const float*)d_in[4];
    const float* W_fc  = (const float*)d_in[5];
    const float* b_fc  = (const float*)d_in[6];
    // d_in[7] = future (static 0) — ignored.

    lstm_bf16_kernel<<<NBLOCKS, NTHREADS>>>(
        input, W_ih, W_hh, b_ih, b_hh, W_fc, b_fc, (float*)d_out);
}

// round 6
// speedup vs baseline: 4.4652x; 1.0347x over previous
#include <cuda_runtime.h>
#include <cuda_bf16.h>
#include <cstdint>

#define HID 51
#define SEQL 999
#define NTHREADS 512
#define NBLOCKS 128

// A fragments: [parity][group][kc][s(hi/lo)], each 512B (lane*16 holds a0..a3)
struct SM {
    uint8_t abuf[2][2][4][2][512];
    float   ypart[2][2][7][16];   // [group][parity][gg][batch row in group]
};
__shared__ SM sm;

__device__ __forceinline__ float tanh_a(float x) {
    float y; asm("tanh.approx.f32 %0, %1;" : "=f"(y) : "f"(x)); return y;
}
__device__ __forceinline__ float sigm(float x) {
    return fmaf(tanh_a(0.5f * x), 0.5f, 0.5f);
}
__device__ __forceinline__ void mma_bf16(float* d, const uint32_t* a, const uint32_t* b) {
    asm volatile("mma.sync.aligned.m16n8k16.row.col.f32.bf16.bf16.f32 "
                 "{%0,%1,%2,%3}, {%4,%5,%6,%7}, {%8,%9}, {%0,%1,%2,%3};"
                 : "+f"(d[0]), "+f"(d[1]), "+f"(d[2]), "+f"(d[3])
                 : "r"(a[0]), "r"(a[1]), "r"(a[2]), "r"(a[3]), "r"(b[0]), "r"(b[1]));
}
// byte offset of A element (row rp 0..15, col kk 0..15) inside a 512B frag
__device__ __forceinline__ int frag_off(int rp, int kk) {
    int lane = (rp & 7) * 4 + ((kk & 7) >> 1);
    int reg  = ((rp >> 3) & 1) + 2 * ((kk >> 3) & 1);
    return lane * 16 + reg * 4 + (kk & 1) * 2;
}
__device__ __forceinline__ uint32_t pkbf2(float v0, float v1) {
    uint32_t a = __bfloat16_as_ushort(__float2bfloat16(v0));
    uint32_t b = __bfloat16_as_ushort(__float2bfloat16(v1));
    return a | (b << 16);
}
#define BARG(g) asm volatile("bar.sync %0, 256;" :: "r"(1 + (g)) : "memory")

__global__ __launch_bounds__(NTHREADS, 1)
void lstm_bf16_kernel(const float* __restrict__ input,
                      const float* __restrict__ W_ih,
                      const float* __restrict__ W_hh,
                      const float* __restrict__ b_ih,
                      const float* __restrict__ b_hh,
                      const float* __restrict__ W_fc,
                      const float* __restrict__ b_fc,
                      float* __restrict__ out)
{
    const int tid = threadIdx.x;
    const int w   = tid >> 5;
    const int l   = tid & 31;
    const int gg  = w >> 1;        // gate group 0..6 (32 interleaved gate cols)
    const int g   = w & 1;         // independent batch-half group
    const int r4  = l & 3;
    const int q   = l >> 2;

    // ---- zero A buffers ----
    {
        uint32_t* p = (uint32_t*)sm.abuf;
        for (int i = tid; i < (int)(sizeof(sm.abuf) / 4); i += NTHREADS) p[i] = 0;
    }
    __syncthreads();
    // bias col (k=52) = 1.0 in both parities; x(0) into parity 0 (k=51)
    if (tid < 32) {
        int grp = tid >> 4, rp = tid & 15;
        for (int par = 0; par < 2; par++)
            *(uint16_t*)&sm.abuf[par][grp][3][0][frag_off(rp, 4)] = 0x3F80; // bf16 1.0
        float x = input[(size_t)(blockIdx.x * 32 + tid) * SEQL];
        __nv_bfloat16 xh = __float2bfloat16(x);
        __nv_bfloat16 xl = __float2bfloat16(x - __bfloat162float(xh));
        *(__nv_bfloat16*)&sm.abuf[0][grp][3][0][frag_off(rp, 3)] = xh;
        *(__nv_bfloat16*)&sm.abuf[0][grp][3][1][frag_off(rp, 3)] = xl;
    }

    // ---- weight fragments into registers (interleaved gate columns) ----
    // col = gg*32 + nt*8 + q maps to hidden j = col>>2, gate qg = col&3,
    // original row = qg*51 + j. (Same weights in both groups.)
    uint32_t wh[4][4][2], wl[4][4][2];
    float wfcj[4];
    if (w < 14) {
        #pragma unroll
        for (int kc = 0; kc < 4; kc++)
        #pragma unroll
        for (int nt = 0; nt < 4; nt++)
        #pragma unroll
        for (int e = 0; e < 2; e++) {
            int col = gg * 32 + nt * 8 + q;
            int j = col >> 2, qg = col & 3;
            int k0 = kc * 16 + r4 * 2 + e * 8;
            float v0 = 0.0f, v1 = 0.0f;
            if (j < HID) {
                int row = qg * HID + j;
                #pragma unroll
                for (int hlf = 0; hlf < 2; hlf++) {
                    int k = k0 + hlf;
                    float v = 0.0f;
                    if (k < HID)       v = W_hh[row * HID + k];
                    else if (k == 51)  v = W_ih[row];
                    else if (k == 52)  v = b_ih[row] + b_hh[row];
                    if (hlf) v1 = v; else v0 = v;
                }
            }
            float h0 = __bfloat162float(__float2bfloat16(v0));
            float h1 = __bfloat162float(__float2bfloat16(v1));
            wh[kc][nt][e] = pkbf2(v0, v1);
            wl[kc][nt][e] = pkbf2(v0 - h0, v1 - h1);
        }
        #pragma unroll
        for (int nt = 0; nt < 4; nt++) {
            int j = gg * 8 + nt * 2 + (r4 >> 1);
            wfcj[nt] = (j < HID) ? W_fc[j] : 0.0f;
        }
    }
    const float bfc = b_fc[0];
    __syncthreads();

    float cst[4] = {0.0f, 0.0f, 0.0f, 0.0f};
    const bool even = !(r4 & 1);
    const int rp_mine = q + (even ? 0 : 8);   // batch row within group tile

    for (int t = 0; t < SEQL; t++) {
        const int par = t & 1;
        if (w < 14) {
            // ---- phase 1: 48 HMMA (bf16 3-term) ----
            float acc[4][4];
            #pragma unroll
            for (int nt = 0; nt < 4; nt++)
            #pragma unroll
            for (int i = 0; i < 4; i++) acc[nt][i] = 0.0f;

            #pragma unroll
            for (int kc = 0; kc < 4; kc++) {
                uint32_t Ah[4], Al[4];
                *(uint4*)Ah = *(const uint4*)&sm.abuf[par][g][kc][0][l * 16];
                *(uint4*)Al = *(const uint4*)&sm.abuf[par][g][kc][1][l * 16];
                #pragma unroll
                for (int nt = 0; nt < 4; nt++) {
                    mma_bf16(acc[nt], Ah, wh[kc][nt]);
                    mma_bf16(acc[nt], Al, wh[kc][nt]);
                    mma_bf16(acc[nt], Ah, wl[kc][nt]);
                }
            }

            // ---- phase 2: in-warp gate exchange + LSTM update ----
            float yp = 0.0f;
            #pragma unroll
            for (int nt = 0; nt < 4; nt++) {
                float v0 = even ? acc[nt][2] : acc[nt][0];
                float v1 = even ? acc[nt][3] : acc[nt][1];
                float e0 = __shfl_xor_sync(0xFFFFFFFFu, v0, 1);
                float e1 = __shfl_xor_sync(0xFFFFFFFFu, v1, 1);
                float gi = even ? acc[nt][0] : e0;
                float gf = even ? acc[nt][1] : e1;
                float gG = even ? e0 : acc[nt][2];
                float gO = even ? e1 : acc[nt][3];
                float cn = fmaf(sigm(gf), cst[nt], sigm(gi) * tanh_a(gG));
                cst[nt] = cn;
                float h = sigm(gO) * tanh_a(cn);
                int j = gg * 8 + nt * 2 + (r4 >> 1);
                if (j < HID) {
                    __nv_bfloat16 hh = __float2bfloat16(h);
                    __nv_bfloat16 hl = __float2bfloat16(h - __bfloat162float(hh));
                    int fo = frag_off(rp_mine, j & 15);
                    *(__nv_bfloat16*)&sm.abuf[par ^ 1][g][j >> 4][0][fo] = hh;
                    *(__nv_bfloat16*)&sm.abuf[par ^ 1][g][j >> 4][1][fo] = hl;
                    yp = fmaf(wfcj[nt], h, yp);
                }
            }
            yp += __shfl_xor_sync(0xFFFFFFFFu, yp, 2);
            if (r4 < 2)
                sm.ypart[g][par][gg][q + r4 * 8] = yp;
            BARG(g);
        } else {
            const int g2 = w - 14;
            // stage x(t+1) into next-parity A; emit y(t-1)
            if (l < 16) {
                if (t + 1 < SEQL) {
                    float x = input[(size_t)(blockIdx.x * 32 + g2 * 16 + l) * SEQL + t + 1];
                    __nv_bfloat16 xh = __float2bfloat16(x);
                    __nv_bfloat16 xl = __float2bfloat16(x - __bfloat162float(xh));
                    int fo = frag_off(l, 3);
                    *(__nv_bfloat16*)&sm.abuf[par ^ 1][g2][3][0][fo] = xh;
                    *(__nv_bfloat16*)&sm.abuf[par ^ 1][g2][3][1][fo] = xl;
                }
                if (t > 0) {
                    float y = bfc;
                    #pragma unroll
                    for (int k = 0; k < 7; k++) y += sm.ypart[g2][par ^ 1][k][l];
                    out[(size_t)(blockIdx.x * 32 + g2 * 16 + l) * SEQL + (t - 1)] = y;
                }
            }
            BARG(g2);
        }
    }

    // final y(SEQL-1) (last BARG already ordered the producer stores)
    if (w >= 14 && l < 16) {
        const int g2 = w - 14;
        float y = bfc;
        #pragma unroll
        for (int k = 0; k < 7; k++) y += sm.ypart[g2][(SEQL - 1) & 1][k][l];
        out[(size_t)(blockIdx.x * 32 + g2 * 16 + l) * SEQL + (SEQL - 1)] = y;
    }
}

extern "C" void kernel_launch(void* const* d_in, const int* in_sizes, int n_in,
                              void* d_out, int out_size) {
    const float* input = (const float*)d_in[0];
    const float* W_ih  = (const float*)d_in[1];
    const float* W_hh  = (const float*)d_in[2];
    const float* b_ih  = (const float*)d_in[3];
    const float* b_hh  = (const float*)d_in[4];
    const float* W_fc  = (const float*)d_in[5];
    const float* b_fc  = (const float*)d_in[6];
    // d_in[7] = future (static 0) — ignored.

    lstm_bf16_kernel<<<NBLOCKS, NTHREADS>>>(
        input, W_ih, W_hh, b_ih, b_hh, W_fc, b_fc, (float*)d_out);
}

// round 7
// speedup vs baseline: 5.5875x; 1.2514x over previous
#include <cuda_runtime.h>
#include <cuda_fp16.h>
#include <cstdint>

#define HID 51
#define SEQL 999
#define NTHREADS 448     // 13 MMA warps + 1 aux warp
#define NBLOCKS 128

// A fragments (h_hi only): [parity][mt][kc] x 512B (lane*16 holds a0..a3, fp16)
struct SM {
    uint8_t abuf[2][2][4][512];
    float   ypart[2][13][32];    // [parity][warp][batch row]
};
__shared__ SM sm;

__device__ __forceinline__ float tanh_a(float x) {
    float y; asm("tanh.approx.f32 %0, %1;" : "=f"(y) : "f"(x)); return y;
}
__device__ __forceinline__ float sigm(float x) {
    return fmaf(tanh_a(0.5f * x), 0.5f, 0.5f);
}
__device__ __forceinline__ void mma_fp16(float* d, const uint32_t* a, const uint32_t* b) {
    asm volatile("mma.sync.aligned.m16n8k16.row.col.f32.f16.f16.f32 "
                 "{%0,%1,%2,%3}, {%4,%5,%6,%7}, {%8,%9}, {%0,%1,%2,%3};"
                 : "+f"(d[0]), "+f"(d[1]), "+f"(d[2]), "+f"(d[3])
                 : "r"(a[0]), "r"(a[1]), "r"(a[2]), "r"(a[3]), "r"(b[0]), "r"(b[1]));
}
// byte offset of element (row rp 0..15, col kk 0..15) inside a 512B fp16 A frag
__device__ __forceinline__ int frag_off(int rp, int kk) {
    int lane = (rp & 7) * 4 + ((kk & 7) >> 1);
    int reg  = ((rp >> 3) & 1) + 2 * ((kk >> 3) & 1);
    return lane * 16 + reg * 4 + (kk & 1) * 2;
}
__device__ __forceinline__ uint32_t pkh2(float v0, float v1) {
    __half2 h = __floats2half2_rn(v0, v1);
    return *(uint32_t*)&h;
}

__global__ __launch_bounds__(NTHREADS, 1)
void lstm_fp16_kernel(const float* __restrict__ input,
                      const float* __restrict__ W_ih,
                      const float* __restrict__ W_hh,
                      const float* __restrict__ b_ih,
                      const float* __restrict__ b_hh,
                      const float* __restrict__ W_fc,
                      const float* __restrict__ b_fc,
                      float* __restrict__ out)
{
    const int tid = threadIdx.x;
    const int w   = tid >> 5;
    const int l   = tid & 31;
    const int r4  = l & 3;
    const int q   = l >> 2;

    // ---- zero A buffers ----
    {
        uint32_t* p = (uint32_t*)sm.abuf;
        for (int i = tid; i < (int)(sizeof(sm.abuf) / 4); i += NTHREADS) p[i] = 0;
    }
    __syncthreads();
    // bias col (k=52, kk=4) = 1.0 both parities; x(0) (k=51, kk=3) parity 0
    if (tid < 32) {
        int grp = tid >> 4, rp = tid & 15;
        for (int par = 0; par < 2; par++)
            *(uint16_t*)&sm.abuf[par][grp][3][frag_off(rp, 4)] = 0x3C00; // fp16 1.0
        float x = input[(size_t)(blockIdx.x * 32 + tid) * SEQL];
        *(__half*)&sm.abuf[0][grp][3][frag_off(rp, 3)] = __float2half_rn(x);
    }

    // ---- weight fragments (fp16 hi/lo) into registers ----
    // col = w*16 + nt*8 + q -> hidden j = col>>2, gate qg = col&3, row = qg*51 + j
    uint32_t wh[4][2][2], wl[4][2][2];
    float wfcj[2];
    if (w < 13) {
        #pragma unroll
        for (int kc = 0; kc < 4; kc++)
        #pragma unroll
        for (int nt = 0; nt < 2; nt++)
        #pragma unroll
        for (int e = 0; e < 2; e++) {
            int col = w * 16 + nt * 8 + q;
            int j = col >> 2, qg = col & 3;
            int k0 = kc * 16 + r4 * 2 + e * 8;
            float v0 = 0.0f, v1 = 0.0f;
            if (j < HID) {
                int row = qg * HID + j;
                #pragma unroll
                for (int hlf = 0; hlf < 2; hlf++) {
                    int k = k0 + hlf;
                    float v = 0.0f;
                    if (k < HID)       v = W_hh[row * HID + k];
                    else if (k == 51)  v = W_ih[row];
                    else if (k == 52)  v = b_ih[row] + b_hh[row];
                    if (hlf) v1 = v; else v0 = v;
                }
            }
            float h0 = __half2float(__float2half_rn(v0));
            float h1 = __half2float(__float2half_rn(v1));
            wh[kc][nt][e] = pkh2(v0, v1);
            wl[kc][nt][e] = pkh2(v0 - h0, v1 - h1);
        }
        #pragma unroll
        for (int nt = 0; nt < 2; nt++) {
            int j = w * 4 + nt * 2 + (r4 >> 1);
            wfcj[nt] = (j < HID) ? W_fc[j] : 0.0f;
        }
    }
    const float bfc = b_fc[0];
    __syncthreads();

    const bool even = !(r4 & 1);
    const int rp_mine = q + (even ? 0 : 8);
    float cst[4] = {0.0f, 0.0f, 0.0f, 0.0f};

    // aux warp prefetch register: x(t+1)
    float xnext = 0.0f;
    if (w == 13 && SEQL > 1)
        xnext = input[(size_t)(blockIdx.x * 32 + l) * SEQL + 1];

    for (int t = 0; t < SEQL; t++) {
        const int par = t & 1;
        if (w < 13) {
            // ---- phase 1: 32 HMMA (fp16 2-term), both batch halves ----
            float acc[2][2][4];
            #pragma unroll
            for (int mt = 0; mt < 2; mt++)
            #pragma unroll
            for (int nt = 0; nt < 2; nt++)
            #pragma unroll
            for (int i = 0; i < 4; i++) acc[mt][nt][i] = 0.0f;

            #pragma unroll
            for (int kc = 0; kc < 4; kc++) {
                uint32_t A0[4], A1[4];
                *(uint4*)A0 = *(const uint4*)&sm.abuf[par][0][kc][l * 16];
                *(uint4*)A1 = *(const uint4*)&sm.abuf[par][1][kc][l * 16];
                #pragma unroll
                for (int nt = 0; nt < 2; nt++) {
                    mma_fp16(acc[0][nt], A0, wh[kc][nt]);
                    mma_fp16(acc[1][nt], A1, wh[kc][nt]);
                    mma_fp16(acc[0][nt], A0, wl[kc][nt]);
                    mma_fp16(acc[1][nt], A1, wl[kc][nt]);
                }
            }

            // ---- phase 2: in-warp gate exchange + LSTM update ----
            float yp[2] = {0.0f, 0.0f};
            #pragma unroll
            for (int mt = 0; mt < 2; mt++)
            #pragma unroll
            for (int nt = 0; nt < 2; nt++) {
                float v0 = even ? acc[mt][nt][2] : acc[mt][nt][0];
                float v1 = even ? acc[mt][nt][3] : acc[mt][nt][1];
                float e0 = __shfl_xor_sync(0xFFFFFFFFu, v0, 1);
                float e1 = __shfl_xor_sync(0xFFFFFFFFu, v1, 1);
                float gi = even ? acc[mt][nt][0] : e0;
                float gf = even ? acc[mt][nt][1] : e1;
                float gG = even ? e0 : acc[mt][nt][2];
                float gO = even ? e1 : acc[mt][nt][3];
                int j = w * 4 + nt * 2 + (r4 >> 1);
                int ci = mt * 2 + nt;
                float cn = fmaf(sigm(gf), cst[ci], sigm(gi) * tanh_a(gG));
                cst[ci] = cn;
                float h = sigm(gO) * tanh_a(cn);
                if (j < HID) {
                    *(__half*)&sm.abuf[par ^ 1][mt][j >> 4][frag_off(rp_mine, j & 15)] =
                        __float2half_rn(h);
                    yp[mt] = fmaf(wfcj[nt], h, yp[mt]);
                }
            }
            yp[0] += __shfl_xor_sync(0xFFFFFFFFu, yp[0], 2);
            yp[1] += __shfl_xor_sync(0xFFFFFFFFu, yp[1], 2);
            if (r4 < 2) {
                sm.ypart[par][w][q + r4 * 8]      = yp[0];
                sm.ypart[par][w][16 + q + r4 * 8] = yp[1];
            }
        } else {
            // ---- aux warp: stage x(t+1) (prefetched), emit y(t-1), prefetch x(t+2)
            if (t + 1 < SEQL)
                *(__half*)&sm.abuf[par ^ 1][l >> 4][3][frag_off(l & 15, 3)] =
                    __float2half_rn(xnext);
            if (t + 2 < SEQL)
                xnext = input[(size_t)(blockIdx.x * 32 + l) * SEQL + t + 2];
            if (t > 0) {
                float y = bfc;
                #pragma unroll
                for (int k = 0; k < 13; k++) y += sm.ypart[par ^ 1][k][l];
                out[(size_t)(blockIdx.x * 32 + l) * SEQL + (t - 1)] = y;
            }
        }
        __syncthreads();
    }

    // final y(SEQL-1)
    if (w == 13) {
        float y = bfc;
        #pragma unroll
        for (int k = 0; k < 13; k++) y += sm.ypart[(SEQL - 1) & 1][k][l];
        out[(size_t)(blockIdx.x * 32 + l) * SEQL + (SEQL - 1)] = y;
    }
}

extern "C" void kernel_launch(void* const* d_in, const int* in_sizes, int n_in,
                              void* d_out, int out_size) {
    const float* input = (const float*)d_in[0];
    const float* W_ih  = (const float*)d_in[1];
    const float* W_hh  = (const float*)d_in[2];
    const float* b_ih  = (const float*)d_in[3];
    const float* b_hh  = (const float*)d_in[4];
    const float* W_fc  = (const float*)d_in[5];
    const float* b_fc  = (const float*)d_in[6];
    // d_in[7] = future (static 0) — ignored.

    lstm_fp16_kernel<<<NBLOCKS, NTHREADS>>>(
        input, W_ih, W_hh, b_ih, b_hh, W_fc, b_fc, (float*)d_out);
}

// round 8
// speedup vs baseline: 6.6470x; 1.1896x over previous
#include <cuda_runtime.h>
#include <cuda_fp16.h>
#include <cstdint>

#define HID 51
#define SEQL 999
#define NTHREADS 256     // 7 MMA warps + 1 aux warp
#define NBLOCKS 256      // 16 batch rows per CTA -> 2 CTAs per SM

// A fragments (h_hi only): [parity][kc] x 512B (lane*16 holds a0..a3, fp16, M=16)
struct SM {
    uint8_t abuf[2][4][512];
    float   ypart[2][7][16];    // [parity][warp][batch row]
};
__shared__ SM sm;

__device__ __forceinline__ float tanh_a(float x) {
    float y; asm("tanh.approx.f32 %0, %1;" : "=f"(y) : "f"(x)); return y;
}
__device__ __forceinline__ float sigm(float x) {
    return fmaf(tanh_a(0.5f * x), 0.5f, 0.5f);
}
__device__ __forceinline__ void mma_fp16(float* d, const uint32_t* a, const uint32_t* b) {
    asm volatile("mma.sync.aligned.m16n8k16.row.col.f32.f16.f16.f32 "
                 "{%0,%1,%2,%3}, {%4,%5,%6,%7}, {%8,%9}, {%0,%1,%2,%3};"
                 : "+f"(d[0]), "+f"(d[1]), "+f"(d[2]), "+f"(d[3])
                 : "r"(a[0]), "r"(a[1]), "r"(a[2]), "r"(a[3]), "r"(b[0]), "r"(b[1]));
}
// byte offset of element (row rp 0..15, col kk 0..15) inside a 512B fp16 A frag
__device__ __forceinline__ int frag_off(int rp, int kk) {
    int lane = (rp & 7) * 4 + ((kk & 7) >> 1);
    int reg  = ((rp >> 3) & 1) + 2 * ((kk >> 3) & 1);
    return lane * 16 + reg * 4 + (kk & 1) * 2;
}
__device__ __forceinline__ uint32_t pkh2(float v0, float v1) {
    __half2 h = __floats2half2_rn(v0, v1);
    return *(uint32_t*)&h;
}

__global__ __launch_bounds__(NTHREADS, 2)
void lstm_fp16_kernel(const float* __restrict__ input,
                      const float* __restrict__ W_ih,
                      const float* __restrict__ W_hh,
                      const float* __restrict__ b_ih,
                      const float* __restrict__ b_hh,
                      const float* __restrict__ W_fc,
                      const float* __restrict__ b_fc,
                      float* __restrict__ out)
{
    const int tid = threadIdx.x;
    const int w   = tid >> 5;
    const int l   = tid & 31;
    const int r4  = l & 3;
    const int q   = l >> 2;
    const int bbase = blockIdx.x * 16;

    // ---- zero A buffers ----
    {
        uint32_t* p = (uint32_t*)sm.abuf;
        for (int i = tid; i < (int)(sizeof(sm.abuf) / 4); i += NTHREADS) p[i] = 0;
    }
    __syncthreads();
    // bias col (k=52, kk=4) = 1.0 both parities; x(0) (k=51, kk=3) parity 0
    if (tid < 16) {
        int rp = tid;
        for (int par = 0; par < 2; par++)
            *(uint16_t*)&sm.abuf[par][3][frag_off(rp, 4)] = 0x3C00; // fp16 1.0
        float x = input[(size_t)(bbase + tid) * SEQL];
        *(__half*)&sm.abuf[0][3][frag_off(rp, 3)] = __float2half_rn(x);
    }

    // ---- weight fragments (fp16 hi/lo) into registers ----
    // col = w*32 + nt*8 + q -> hidden j = col>>2, gate qg = col&3, row = qg*51 + j
    uint32_t wh[4][4][2], wl[4][4][2];
    float wfcj[4];
    if (w < 7) {
        #pragma unroll
        for (int kc = 0; kc < 4; kc++)
        #pragma unroll
        for (int nt = 0; nt < 4; nt++)
        #pragma unroll
        for (int e = 0; e < 2; e++) {
            int col = w * 32 + nt * 8 + q;
            int j = col >> 2, qg = col & 3;
            int k0 = kc * 16 + r4 * 2 + e * 8;
            float v0 = 0.0f, v1 = 0.0f;
            if (j < HID) {
                int row = qg * HID + j;
                #pragma unroll
                for (int hlf = 0; hlf < 2; hlf++) {
                    int k = k0 + hlf;
                    float v = 0.0f;
                    if (k < HID)       v = W_hh[row * HID + k];
                    else if (k == 51)  v = W_ih[row];
                    else if (k == 52)  v = b_ih[row] + b_hh[row];
                    if (hlf) v1 = v; else v0 = v;
                }
            }
            float h0 = __half2float(__float2half_rn(v0));
            float h1 = __half2float(__float2half_rn(v1));
            wh[kc][nt][e] = pkh2(v0, v1);
            wl[kc][nt][e] = pkh2(v0 - h0, v1 - h1);
        }
        #pragma unroll
        for (int nt = 0; nt < 4; nt++) {
            int j = w * 8 + nt * 2 + (r4 >> 1);
            wfcj[nt] = (j < HID) ? W_fc[j] : 0.0f;
        }
    }
    const float bfc = b_fc[0];
    __syncthreads();

    const bool even = !(r4 & 1);
    const int rp_mine = q + (even ? 0 : 8);
    float cst[4] = {0.0f, 0.0f, 0.0f, 0.0f};

    // aux warp prefetch register: x(t+1)
    float xnext = 0.0f;
    if (w == 7 && l < 16 && SEQL > 1)
        xnext = input[(size_t)(bbase + l) * SEQL + 1];

    for (int t = 0; t < SEQL; t++) {
        const int par = t & 1;
        if (w < 7) {
            // ---- phase 1: 32 HMMA (fp16 2-term, 4 n-tiles) ----
            float acc[4][4];
            #pragma unroll
            for (int nt = 0; nt < 4; nt++)
            #pragma unroll
            for (int i = 0; i < 4; i++) acc[nt][i] = 0.0f;

            #pragma unroll
            for (int kc = 0; kc < 4; kc++) {
                uint32_t A[4];
                *(uint4*)A = *(const uint4*)&sm.abuf[par][kc][l * 16];
                #pragma unroll
                for (int nt = 0; nt < 4; nt++) {
                    mma_fp16(acc[nt], A, wh[kc][nt]);
                    mma_fp16(acc[nt], A, wl[kc][nt]);
                }
            }

            // ---- phase 2: in-warp gate exchange + LSTM update ----
            float yp = 0.0f;
            #pragma unroll
            for (int nt = 0; nt < 4; nt++) {
                float v0 = even ? acc[nt][2] : acc[nt][0];
                float v1 = even ? acc[nt][3] : acc[nt][1];
                float e0 = __shfl_xor_sync(0xFFFFFFFFu, v0, 1);
                float e1 = __shfl_xor_sync(0xFFFFFFFFu, v1, 1);
                float gi = even ? acc[nt][0] : e0;
                float gf = even ? acc[nt][1] : e1;
                float gG = even ? e0 : acc[nt][2];
                float gO = even ? e1 : acc[nt][3];
                int j = w * 8 + nt * 2 + (r4 >> 1);
                float cn = fmaf(sigm(gf), cst[nt], sigm(gi) * tanh_a(gG));
                cst[nt] = cn;
                float h = sigm(gO) * tanh_a(cn);
                if (j < HID) {
                    *(__half*)&sm.abuf[par ^ 1][j >> 4][frag_off(rp_mine, j & 15)] =
                        __float2half_rn(h);
                    yp = fmaf(wfcj[nt], h, yp);
                }
            }
            yp += __shfl_xor_sync(0xFFFFFFFFu, yp, 2);
            if (r4 < 2)
                sm.ypart[par][w][q + r4 * 8] = yp;
        } else if (l < 16) {
            // ---- aux warp: stage x(t+1) (prefetched), emit y(t-1), prefetch x(t+2)
            if (t + 1 < SEQL)
                *(__half*)&sm.abuf[par ^ 1][3][frag_off(l, 3)] = __float2half_rn(xnext);
            if (t + 2 < SEQL)
                xnext = input[(size_t)(bbase + l) * SEQL + t + 2];
            if (t > 0) {
                float y = bfc;
                #pragma unroll
                for (int k = 0; k < 7; k++) y += sm.ypart[par ^ 1][k][l];
                out[(size_t)(bbase + l) * SEQL + (t - 1)] = y;
            }
        }
        __syncthreads();
    }

    // final y(SEQL-1)
    if (w == 7 && l < 16) {
        float y = bfc;
        #pragma unroll
        for (int k = 0; k < 7; k++) y += sm.ypart[(SEQL - 1) & 1][k][l];
        out[(size_t)(bbase + l) * SEQL + (SEQL - 1)] = y;
    }
}

extern "C" void kernel_launch(void* const* d_in, const int* in_sizes, int n_in,
                              void* d_out, int out_size) {
    const float* input = (const float*)d_in[0];
    const float* W_ih  = (const float*)d_in[1];
    const float* W_hh  = (const float*)d_in[2];
    const float* b_ih  = (const float*)d_in[3];
    const float* b_hh  = (const float*)d_in[4];
    const float* W_fc  = (const float*)d_in[5];
    const float* b_fc  = (const float*)d_in[6];
    // d_in[7] = future (static 0) — ignored.

    lstm_fp16_kernel<<<NBLOCKS, NTHREADS>>>(
        input, W_ih, W_hh, b_ih, b_hh, W_fc, b_fc, (float*)d_out);
}